// round 2
// baseline (speedup 1.0000x reference)
#include <cuda_runtime.h>
#include <cuda_bf16.h>
#include <stdint.h>

#define L 4096
#define NB 4

// Normalized int32 copy of seq_ids (handles both int64 and int32 input encodings).
__device__ int g_seq32[L];

// Detect element width of the id tensor and normalize to int32.
// int64 data: words alternate (value, 0) with value in 0..3.
// int32 data: reading the first 16 values as int64 yields v0 + v1*2^32, which
// exceeds 3 unless every odd word is 0 AND even word <=3  (prob ~ (1/4)^16*(1/4)^16).
__global__ void normalize_seq_kernel(const int* __restrict__ raw) {
    __shared__ int is64;
    if (threadIdx.x == 0) {
        const long long* p = reinterpret_cast<const long long*>(raw);
        int ok = 1;
        #pragma unroll
        for (int k = 0; k < 16; k++) {
            long long v = p[k];
            if (v < 0 || v > 3) { ok = 0; break; }
        }
        is64 = ok;
    }
    __syncthreads();
    const long long* p64 = reinterpret_cast<const long long*>(raw);
    for (int idx = threadIdx.x; idx < L; idx += blockDim.x) {
        int v = is64 ? (int)p64[idx] : raw[idx];
        g_seq32[idx] = v;
    }
}

// Pure write kernel: one float4 (STG.128, streaming) per thread.
// t in [0, 8*4096*4096/4):  j4 = t & 1023, i = (t>>10) & 4095, c = t >> 22.
//   c in [0,4):  out row is broadcast of (seq[i]==c)
//   c in [4,8):  out quad is one-hot compare of seq[4*j4 .. 4*j4+3] vs (c-4)
__global__ void __launch_bounds__(256) seq_embed_fill_kernel(float4* __restrict__ out) {
    unsigned int t = blockIdx.x * 256u + threadIdx.x;
    unsigned int j4 = t & 1023u;
    unsigned int i  = (t >> 10) & 4095u;
    unsigned int c  = t >> 22;

    float4 v;
    if (c < 4u) {
        float x = (g_seq32[i] == (int)c) ? 1.0f : 0.0f;
        v.x = x; v.y = x; v.z = x; v.w = x;
    } else {
        int cc = (int)c - 4;
        int4 s = reinterpret_cast<const int4*>(g_seq32)[j4];
        v.x = (s.x == cc) ? 1.0f : 0.0f;
        v.y = (s.y == cc) ? 1.0f : 0.0f;
        v.z = (s.z == cc) ? 1.0f : 0.0f;
        v.w = (s.w == cc) ? 1.0f : 0.0f;
    }
    __stcs(out + t, v);   // streaming store: bypass L2 persistence, pure write-through
}

extern "C" void kernel_launch(void* const* d_in, const int* in_sizes, int n_in,
                              void* d_out, int out_size) {
    const int* raw_seq = (const int*)d_in[0];   // seq_ids (int64 or int32, auto-detected)
    // d_in[1] is base_table (identity eye(4)) — not needed, comparisons suffice.

    normalize_seq_kernel<<<1, 256>>>(raw_seq);

    // total float4 elements = 8 * 4096 * 4096 / 4 = 2^25
    unsigned int total4 = (unsigned int)(8u * (unsigned)L * (unsigned)L / 4u);
    unsigned int blocks = total4 / 256u;   // 131072
    seq_embed_fill_kernel<<<blocks, 256>>>((float4*)d_out);
}